// round 6
// baseline (speedup 1.0000x reference)
#include <cuda_runtime.h>

// Problem constants
#define NN 69          // nodes
#define NP 72          // padded nodes (multiple of 4)
#define FIN 8
#define H1C 32
#define H2C 16
#define TB 16          // bt instances per block
#define NTHREADS 288   // 18 node-groups(4) x 16 t
#define GSTR 260       // padded row stride for g tile (TB*H2C + 4)
#define BT_TOTAL 32768 // B*T

__device__ float g_adjn[NP * NP];   // normalized adjacency, zero padded, symmetric

// ---------------------------------------------------------------------------
// Prep: adj_n = D^-1/2 (A + I) D^-1/2, padded to 72x72 with zeros
// ---------------------------------------------------------------------------
__global__ void prep_kernel(const float* __restrict__ adj) {
    __shared__ float dis[NN];
    int tid = threadIdx.x;
    if (tid < NN) {
        float s = 1.0f;                      // +I diagonal
        for (int m = 0; m < NN; m++) s += adj[tid * NN + m];
        dis[tid] = rsqrtf(s);
    }
    __syncthreads();
    for (int idx = tid; idx < NP * NP; idx += blockDim.x) {
        int n = idx / NP, m = idx % NP;
        float v = 0.0f;
        if (n < NN && m < NN) {
            float a = adj[n * NN + m] + (n == m ? 1.0f : 0.0f);
            v = a * dis[n] * dis[m];
        }
        g_adjn[idx] = v;
    }
}

// ---------------------------------------------------------------------------
// Fused GCN: per block, TB bt-instances through both layers.
//   S1 = adj_n @ x          (over F=8)
//   h  = relu(S1 @ W1)
//   g  = h @ W2             (associativity: apply W2 BEFORE 2nd propagation)
//   out= sigmoid(adj_n @ g) (over H2=16)
// ---------------------------------------------------------------------------
__global__ __launch_bounds__(NTHREADS) void gcn_fused(
        const float* __restrict__ x,
        const float* __restrict__ W1,
        const float* __restrict__ W2,
        float* __restrict__ out) {
    extern __shared__ float sm[];
    float* adjn_s = sm;                        // NP*NP   = 5184
    float* W1t    = adjn_s + NP * NP;          // 256  (W1t[j*8+f] = W1[f][j])
    float* W2s    = W1t + FIN * H1C;           // 512  (W2s[j*16+k])
    float* xs     = W2s + H1C * H2C;           // NN*TB*FIN = 8832
    float* gs     = xs + NN * TB * FIN;        // NP*GSTR = 18720

    const int tid = threadIdx.x;
    const int bt0 = blockIdx.x * TB;

    // --- stage shared operands ---
    for (int i = tid; i < NP * NP; i += NTHREADS) adjn_s[i] = g_adjn[i];
    for (int i = tid; i < FIN * H1C; i += NTHREADS) {
        int j = i >> 3, f = i & 7;
        W1t[i] = W1[f * H1C + j];
    }
    for (int i = tid; i < H1C * H2C; i += NTHREADS) W2s[i] = W2[i];
    // x[m, bt, f], bt-contiguous: 128 consecutive floats per node row
    for (int i = tid; i < NN * TB * FIN; i += NTHREADS) {
        int m = i >> 7, c = i & 127;
        xs[i] = x[m * (BT_TOTAL * FIN) + bt0 * FIN + c];
    }
    __syncthreads();

    const int t  = tid & (TB - 1);
    const int n0 = (tid >> 4) * 4;   // 0,4,...,68 (covers padded 72 nodes)

    // --- step 2: S1[n0..n0+3][0..7] = sum_m adjn[n][m] * x[m][t][f] ---
    float acc[4][FIN];
    #pragma unroll
    for (int i = 0; i < 4; i++)
        #pragma unroll
        for (int f = 0; f < FIN; f++) acc[i][f] = 0.0f;

    const float* xrow = xs + t * FIN;
    #pragma unroll 4
    for (int m = 0; m < NN; m++) {
        float4 a  = *(const float4*)(adjn_s + m * NP + n0);   // symmetric: adjn[n][m]
        float4 x0 = *(const float4*)(xrow + m * (TB * FIN));
        float4 x1 = *(const float4*)(xrow + m * (TB * FIN) + 4);
        float av[4] = {a.x, a.y, a.z, a.w};
        float xv[8] = {x0.x, x0.y, x0.z, x0.w, x1.x, x1.y, x1.z, x1.w};
        #pragma unroll
        for (int i = 0; i < 4; i++)
            #pragma unroll
            for (int f = 0; f < FIN; f++)
                acc[i][f] = fmaf(av[i], xv[f], acc[i][f]);
    }

    // --- steps 3-4: g = relu(S1 @ W1) @ W2, stored to shared ---
    #pragma unroll
    for (int i = 0; i < 4; i++) {
        float g[H2C];
        #pragma unroll
        for (int k = 0; k < H2C; k++) g[k] = 0.0f;
        #pragma unroll 8
        for (int j = 0; j < H1C; j++) {
            float4 w1a = *(const float4*)(W1t + j * FIN);
            float4 w1b = *(const float4*)(W1t + j * FIN + 4);
            float h = acc[i][0] * w1a.x;
            h = fmaf(acc[i][1], w1a.y, h);
            h = fmaf(acc[i][2], w1a.z, h);
            h = fmaf(acc[i][3], w1a.w, h);
            h = fmaf(acc[i][4], w1b.x, h);
            h = fmaf(acc[i][5], w1b.y, h);
            h = fmaf(acc[i][6], w1b.z, h);
            h = fmaf(acc[i][7], w1b.w, h);
            h = fmaxf(h, 0.0f);
            #pragma unroll
            for (int q = 0; q < 4; q++) {
                float4 w2 = *(const float4*)(W2s + j * H2C + q * 4);
                g[q*4+0] = fmaf(h, w2.x, g[q*4+0]);
                g[q*4+1] = fmaf(h, w2.y, g[q*4+1]);
                g[q*4+2] = fmaf(h, w2.z, g[q*4+2]);
                g[q*4+3] = fmaf(h, w2.w, g[q*4+3]);
            }
        }
        float* grow = gs + (n0 + i) * GSTR + t * H2C;
        #pragma unroll
        for (int q = 0; q < 4; q++)
            *(float4*)(grow + q * 4) =
                make_float4(g[q*4], g[q*4+1], g[q*4+2], g[q*4+3]);
    }
    __syncthreads();

    // --- step 5: out = sigmoid(adjn @ g) ---
    float o[4][H2C];
    #pragma unroll
    for (int i = 0; i < 4; i++)
        #pragma unroll
        for (int k = 0; k < H2C; k++) o[i][k] = 0.0f;

    const float* gcol = gs + t * H2C;
    #pragma unroll 2
    for (int m = 0; m < NN; m++) {
        float4 a = *(const float4*)(adjn_s + m * NP + n0);
        float av[4] = {a.x, a.y, a.z, a.w};
        float gv[H2C];
        #pragma unroll
        for (int q = 0; q < 4; q++) {
            float4 gq = *(const float4*)(gcol + m * GSTR + q * 4);
            gv[q*4+0] = gq.x; gv[q*4+1] = gq.y;
            gv[q*4+2] = gq.z; gv[q*4+3] = gq.w;
        }
        #pragma unroll
        for (int i = 0; i < 4; i++)
            #pragma unroll
            for (int k = 0; k < H2C; k++)
                o[i][k] = fmaf(av[i], gv[k], o[i][k]);
    }

    const int bt = bt0 + t;
    #pragma unroll
    for (int i = 0; i < 4; i++) {
        int n = n0 + i;
        if (n < NN) {                       // skip padded nodes 69..71
            float* op = out + ((size_t)bt * NN + n) * H2C;
            #pragma unroll
            for (int q = 0; q < 4; q++) {
                float4 r;
                r.x = 1.0f / (1.0f + __expf(-o[i][q*4+0]));
                r.y = 1.0f / (1.0f + __expf(-o[i][q*4+1]));
                r.z = 1.0f / (1.0f + __expf(-o[i][q*4+2]));
                r.w = 1.0f / (1.0f + __expf(-o[i][q*4+3]));
                *(float4*)(op + q * 4) = r;   // 64B-aligned full sectors
            }
        }
    }
}

// ---------------------------------------------------------------------------
extern "C" void kernel_launch(void* const* d_in, const int* in_sizes, int n_in,
                              void* d_out, int out_size) {
    const float* x   = (const float*)d_in[0];
    const float* adj = (const float*)d_in[1];
    const float* W1  = (const float*)d_in[2];
    const float* W2  = (const float*)d_in[3];
    float* out = (float*)d_out;

    const size_t smem =
        (size_t)(NP * NP + FIN * H1C + H1C * H2C + NN * TB * FIN + NP * GSTR) *
        sizeof(float);   // 134016 B -> 1 block/SM
    cudaFuncSetAttribute(gcn_fused,
                         cudaFuncAttributeMaxDynamicSharedMemorySize,
                         (int)smem);

    prep_kernel<<<1, 128>>>(adj);
    gcn_fused<<<BT_TOTAL / TB, NTHREADS, smem>>>(x, W1, W2, out);
}

// round 10
// speedup vs baseline: 1.8301x; 1.8301x over previous
#include <cuda_runtime.h>
#include <cuda_fp16.h>

// Problem constants
#define NN 69          // nodes
#define NP 72          // padded nodes (multiple of 4)
#define FIN 8
#define H1C 32
#define H2C 16
#define TB 32          // bt instances per block
#define NTHREADS 576   // 18 node-groups(4) x 32 t  -> 18 warps/SM
#define XSTR 552       // halves per t-row of x tile (NN*8); words 276 = 4 mod 8 -> conflict-free
#define MSTR 1160      // halves per t-row of g tile (NP*16+8); words 580 = 4 mod 8 -> conflict-free
#define BT_TOTAL 32768 // B*T

__device__ float g_adjn[NP * NP];   // normalized adjacency, zero padded, symmetric

// ---------------------------------------------------------------------------
// Prep: adj_n = D^-1/2 (A + I) D^-1/2, padded to 72x72 with zeros
// ---------------------------------------------------------------------------
__global__ void prep_kernel(const float* __restrict__ adj) {
    __shared__ float dis[NN];
    int tid = threadIdx.x;
    if (tid < NN) {
        float s = 1.0f;                      // +I diagonal
        for (int m = 0; m < NN; m++) s += adj[tid * NN + m];
        dis[tid] = rsqrtf(s);
    }
    __syncthreads();
    for (int idx = tid; idx < NP * NP; idx += blockDim.x) {
        int n = idx / NP, m = idx % NP;
        float v = 0.0f;
        if (n < NN && m < NN) {
            float a = adj[n * NN + m] + (n == m ? 1.0f : 0.0f);
            v = a * dis[n] * dis[m];
        }
        g_adjn[idx] = v;
    }
}

__device__ __forceinline__ unsigned int h2u(__half2 h) {
    return *reinterpret_cast<unsigned int*>(&h);
}

// ---------------------------------------------------------------------------
// Fused GCN. Per block: TB=32 bt-instances through both layers.
//   S1 = adj_n @ x            (over F=8)
//   h  = relu(S1 @ W1)
//   g  = h @ W2               (associativity: W2 applied BEFORE 2nd prop)
//   out= sigmoid(adj_n @ g)   (over H2=16)
// Warp = 32 t's of one node-group -> adjn loads are warp broadcasts.
// x and g tiles stored fp16 [t][m] with conflict-free strides; math fp32.
// ---------------------------------------------------------------------------
__global__ __launch_bounds__(NTHREADS) void gcn_fused(
        const float* __restrict__ x,
        const float* __restrict__ W1,
        const float* __restrict__ W2,
        float* __restrict__ out) {
    extern __shared__ float sm[];
    float*  adjn_s = sm;                           // 5184 f
    float*  W1t    = adjn_s + NP * NP;             // 256 f  (W1t[j*8+f] = W1[f][j])
    float*  W2s    = W1t + FIN * H1C;              // 512 f  (W2s[j*16+k])
    __half* xs     = (__half*)(W2s + H1C * H2C);   // TB*XSTR halves
    __half* gs     = xs + TB * XSTR;               // TB*MSTR halves

    const int tid = threadIdx.x;
    const int bt0 = blockIdx.x * TB;

    // --- stage shared operands ---
    for (int i = tid; i < NP * NP; i += NTHREADS) adjn_s[i] = g_adjn[i];
    for (int i = tid; i < FIN * H1C; i += NTHREADS) {
        int j = i >> 3, f = i & 7;
        W1t[i] = W1[f * H1C + j];
    }
    for (int i = tid; i < H1C * H2C; i += NTHREADS) W2s[i] = W2[i];
    // x[m, bt, f]: each (m,t) is 8 consecutive floats -> 2 float4, cvt to 8 halves
    for (int i = tid; i < NN * TB; i += NTHREADS) {
        int m = i >> 5, t = i & (TB - 1);
        const float4* src =
            (const float4*)(x + (size_t)m * (BT_TOTAL * FIN) + (size_t)(bt0 + t) * FIN);
        float4 a = src[0], b = src[1];
        uint4 u;
        u.x = h2u(__floats2half2_rn(a.x, a.y));
        u.y = h2u(__floats2half2_rn(a.z, a.w));
        u.z = h2u(__floats2half2_rn(b.x, b.y));
        u.w = h2u(__floats2half2_rn(b.z, b.w));
        *(uint4*)(xs + (size_t)t * XSTR + m * FIN) = u;
    }
    __syncthreads();

    const int t  = tid & (TB - 1);       // 0..31 (all 32 t's in one warp)
    const int n0 = (tid >> 5) * 4;       // 0,4,...,68

    // --- step 2: S1[n0..n0+3][0..7] = sum_m adjn[n][m] * x[m][t][f] ---
    float acc[4][FIN];
    #pragma unroll
    for (int i = 0; i < 4; i++)
        #pragma unroll
        for (int f = 0; f < FIN; f++) acc[i][f] = 0.0f;

    const __half* xrow = xs + (size_t)t * XSTR;
    #pragma unroll 4
    for (int m = 0; m < NN; m++) {
        float4 a = *(const float4*)(adjn_s + m * NP + n0);   // warp broadcast
        uint4 xr = *(const uint4*)(xrow + m * FIN);
        float2 f0 = __half22float2(*reinterpret_cast<const __half2*>(&xr.x));
        float2 f1 = __half22float2(*reinterpret_cast<const __half2*>(&xr.y));
        float2 f2 = __half22float2(*reinterpret_cast<const __half2*>(&xr.z));
        float2 f3 = __half22float2(*reinterpret_cast<const __half2*>(&xr.w));
        float av[4] = {a.x, a.y, a.z, a.w};
        float xv[8] = {f0.x, f0.y, f1.x, f1.y, f2.x, f2.y, f3.x, f3.y};
        #pragma unroll
        for (int i = 0; i < 4; i++)
            #pragma unroll
            for (int f = 0; f < FIN; f++)
                acc[i][f] = fmaf(av[i], xv[f], acc[i][f]);
    }

    // --- steps 3-4: g = relu(S1 @ W1) @ W2, stored to shared as fp16 ---
    #pragma unroll
    for (int i = 0; i < 4; i++) {
        float g[H2C];
        #pragma unroll
        for (int k = 0; k < H2C; k++) g[k] = 0.0f;
        #pragma unroll 8
        for (int j = 0; j < H1C; j++) {
            float4 w1a = *(const float4*)(W1t + j * FIN);
            float4 w1b = *(const float4*)(W1t + j * FIN + 4);
            float h = acc[i][0] * w1a.x;
            h = fmaf(acc[i][1], w1a.y, h);
            h = fmaf(acc[i][2], w1a.z, h);
            h = fmaf(acc[i][3], w1a.w, h);
            h = fmaf(acc[i][4], w1b.x, h);
            h = fmaf(acc[i][5], w1b.y, h);
            h = fmaf(acc[i][6], w1b.z, h);
            h = fmaf(acc[i][7], w1b.w, h);
            h = fmaxf(h, 0.0f);
            #pragma unroll
            for (int q = 0; q < 4; q++) {
                float4 w2 = *(const float4*)(W2s + j * H2C + q * 4);
                g[q*4+0] = fmaf(h, w2.x, g[q*4+0]);
                g[q*4+1] = fmaf(h, w2.y, g[q*4+1]);
                g[q*4+2] = fmaf(h, w2.z, g[q*4+2]);
                g[q*4+3] = fmaf(h, w2.w, g[q*4+3]);
            }
        }
        __half* grow = gs + (size_t)t * MSTR + (n0 + i) * H2C;
        uint4 u0, u1;
        u0.x = h2u(__floats2half2_rn(g[0],  g[1]));
        u0.y = h2u(__floats2half2_rn(g[2],  g[3]));
        u0.z = h2u(__floats2half2_rn(g[4],  g[5]));
        u0.w = h2u(__floats2half2_rn(g[6],  g[7]));
        u1.x = h2u(__floats2half2_rn(g[8],  g[9]));
        u1.y = h2u(__floats2half2_rn(g[10], g[11]));
        u1.z = h2u(__floats2half2_rn(g[12], g[13]));
        u1.w = h2u(__floats2half2_rn(g[14], g[15]));
        *(uint4*)(grow)     = u0;
        *(uint4*)(grow + 8) = u1;
    }
    __syncthreads();

    // --- step 5: out = sigmoid(adjn @ g) ---
    float o[4][H2C];
    #pragma unroll
    for (int i = 0; i < 4; i++)
        #pragma unroll
        for (int k = 0; k < H2C; k++) o[i][k] = 0.0f;

    const __half* gcol = gs + (size_t)t * MSTR;
    #pragma unroll 2
    for (int m = 0; m < NN; m++) {
        float4 a = *(const float4*)(adjn_s + m * NP + n0);   // warp broadcast
        uint4 g0 = *(const uint4*)(gcol + m * H2C);
        uint4 g1 = *(const uint4*)(gcol + m * H2C + 8);
        float av[4] = {a.x, a.y, a.z, a.w};
        float gv[H2C];
        {
            float2 p;
            p = __half22float2(*reinterpret_cast<const __half2*>(&g0.x)); gv[0]=p.x;  gv[1]=p.y;
            p = __half22float2(*reinterpret_cast<const __half2*>(&g0.y)); gv[2]=p.x;  gv[3]=p.y;
            p = __half22float2(*reinterpret_cast<const __half2*>(&g0.z)); gv[4]=p.x;  gv[5]=p.y;
            p = __half22float2(*reinterpret_cast<const __half2*>(&g0.w)); gv[6]=p.x;  gv[7]=p.y;
            p = __half22float2(*reinterpret_cast<const __half2*>(&g1.x)); gv[8]=p.x;  gv[9]=p.y;
            p = __half22float2(*reinterpret_cast<const __half2*>(&g1.y)); gv[10]=p.x; gv[11]=p.y;
            p = __half22float2(*reinterpret_cast<const __half2*>(&g1.z)); gv[12]=p.x; gv[13]=p.y;
            p = __half22float2(*reinterpret_cast<const __half2*>(&g1.w)); gv[14]=p.x; gv[15]=p.y;
        }
        #pragma unroll
        for (int i = 0; i < 4; i++)
            #pragma unroll
            for (int k = 0; k < H2C; k++)
                o[i][k] = fmaf(av[i], gv[k], o[i][k]);
    }

    const int bt = bt0 + t;
    #pragma unroll
    for (int i = 0; i < 4; i++) {
        int n = n0 + i;
        if (n < NN) {                       // skip padded nodes 69..71
            float* op = out + ((size_t)bt * NN + n) * H2C;
            #pragma unroll
            for (int q = 0; q < 4; q++) {
                float4 r;
                r.x = 1.0f / (1.0f + __expf(-o[i][q*4+0]));
                r.y = 1.0f / (1.0f + __expf(-o[i][q*4+1]));
                r.z = 1.0f / (1.0f + __expf(-o[i][q*4+2]));
                r.w = 1.0f / (1.0f + __expf(-o[i][q*4+3]));
                *(float4*)(op + q * 4) = r;   // 64B contiguous per (bt,n)
            }
        }
    }
}

// ---------------------------------------------------------------------------
extern "C" void kernel_launch(void* const* d_in, const int* in_sizes, int n_in,
                              void* d_out, int out_size) {
    const float* x   = (const float*)d_in[0];
    const float* adj = (const float*)d_in[1];
    const float* W1  = (const float*)d_in[2];
    const float* W2  = (const float*)d_in[3];
    float* out = (float*)d_out;

    const size_t smem =
        (size_t)(NP * NP + FIN * H1C + H1C * H2C) * sizeof(float) +
        (size_t)(TB * XSTR + TB * MSTR) * sizeof(__half);   // 133376 B
    cudaFuncSetAttribute(gcn_fused,
                         cudaFuncAttributeMaxDynamicSharedMemorySize,
                         (int)smem);

    prep_kernel<<<1, 128>>>(adj);
    gcn_fused<<<BT_TOTAL / TB, NTHREADS, smem>>>(x, W1, W2, out);
}

// round 11
// speedup vs baseline: 2.8087x; 1.5347x over previous
#include <cuda_runtime.h>
#include <cuda_fp16.h>

// Problem constants
#define NN 69          // nodes
#define NP 72          // padded nodes (multiple of 4)
#define FIN 8
#define H1C 32
#define H2C 16
#define TB 32          // bt instances per block
#define NTHREADS 576   // 18 warps; warp = one 4-node group x 32 instances
#define XSTR 552       // halves per t-row of x tile (NN*8); 276 words = 4 mod 8 -> conflict-free
#define GSTR 1156      // floats per t-row of g tile (NP*16+4); = 4 mod 8 -> conflict-free
#define BT_TOTAL 32768 // B*T

// CSR of normalized adjacency (built once by prep_kernel)
__device__ float          g_vals[NP * NP];
__device__ unsigned short g_idxs[NP * NP];
__device__ int            g_deg[NP];

// ---------------------------------------------------------------------------
// Prep: adj_n = D^-1/2 (A + I) D^-1/2, stored as fixed-stride CSR (row n at
// [n*NP, n*NP+deg[n])). Symmetric matrix -> row list == column list.
// ---------------------------------------------------------------------------
__global__ void prep_kernel(const float* __restrict__ adj) {
    __shared__ float dis[NN];
    int tid = threadIdx.x;
    if (tid < NN) {
        float s = 1.0f;                      // +I diagonal
        for (int m = 0; m < NN; m++) s += adj[tid * NN + m];
        dis[tid] = rsqrtf(s);
    }
    __syncthreads();
    if (tid < NP) {
        int d = 0;
        if (tid < NN) {
            for (int m = 0; m < NN; m++) {
                float a = adj[tid * NN + m] + (tid == m ? 1.0f : 0.0f);
                if (a != 0.0f) {
                    g_vals[tid * NP + d] = a * dis[tid] * dis[m];
                    g_idxs[tid * NP + d] = (unsigned short)m;
                    d++;
                }
            }
        }
        g_deg[tid] = d;
    }
}

// ---------------------------------------------------------------------------
// Packed fp32 pair FMA (Blackwell f32x2 pipe: 2 FMAs per issue slot, rt=2)
// ---------------------------------------------------------------------------
__device__ __forceinline__ float2 ffma2(float2 a, float2 b, float2 c) {
    unsigned long long ua = *reinterpret_cast<unsigned long long*>(&a);
    unsigned long long ub = *reinterpret_cast<unsigned long long*>(&b);
    unsigned long long uc = *reinterpret_cast<unsigned long long*>(&c);
    unsigned long long ud;
    asm("fma.rn.f32x2 %0, %1, %2, %3;" : "=l"(ud) : "l"(ua), "l"(ub), "l"(uc));
    return *reinterpret_cast<float2*>(&ud);
}

__device__ __forceinline__ unsigned int h2u(__half2 h) {
    return *reinterpret_cast<unsigned int*>(&h);
}

// ---------------------------------------------------------------------------
// Fused GCN. Per block: TB=32 bt-instances through both layers.
//   S1 = adj_n @ x            (SPARSE, over nonzeros of each row)
//   h  = relu(S1 @ W1)
//   g  = h @ W2               (associativity: W2 applied BEFORE 2nd prop)
//   out= sigmoid(adj_n @ g)   (SPARSE)
// Warp = 32 t's of one 4-node group -> CSR loads are warp broadcasts.
// x tile fp16 [t][m]; g tile fp32 [t][m]; all math fp32 via f32x2 pairs.
// ---------------------------------------------------------------------------
__global__ __launch_bounds__(NTHREADS) void gcn_fused(
        const float* __restrict__ x,
        const float* __restrict__ W1,
        const float* __restrict__ W2,
        float* __restrict__ out) {
    extern __shared__ float sm[];
    float*  gs    = sm;                             // TB*GSTR      = 147968 B
    float*  svals = gs + TB * GSTR;                 // NP*NP        =  20736 B
    float*  W1t   = svals + NP * NP;                // 256 f (W1t[j*8+f]=W1[f][j])
    float*  W2s   = W1t + FIN * H1C;                // 512 f (W2s[j*16+k])
    __half* xs    = (__half*)(W2s + H1C * H2C);     // TB*XSTR      =  35328 B
    unsigned short* sidx = (unsigned short*)(xs + TB * XSTR);  // NP*NP u16
    int*    sdeg  = (int*)(sidx + NP * NP);         // NP

    const int tid = threadIdx.x;
    const int bt0 = blockIdx.x * TB;

    // --- stage shared operands ---
    for (int i = tid; i < NP * NP; i += NTHREADS) svals[i] = g_vals[i];
    for (int i = tid; i < NP * NP; i += NTHREADS) sidx[i]  = g_idxs[i];
    if (tid < NP) sdeg[tid] = g_deg[tid];
    for (int i = tid; i < FIN * H1C; i += NTHREADS) {
        int j = i >> 3, f = i & 7;
        W1t[i] = W1[f * H1C + j];
    }
    for (int i = tid; i < H1C * H2C; i += NTHREADS) W2s[i] = W2[i];
    // x[m, bt, f]: 8 consecutive floats per (m,t) -> 8 halves
    for (int i = tid; i < NN * TB; i += NTHREADS) {
        int m = i >> 5, t = i & (TB - 1);
        const float4* src =
            (const float4*)(x + (size_t)m * (BT_TOTAL * FIN) + (size_t)(bt0 + t) * FIN);
        float4 a = src[0], b = src[1];
        uint4 u;
        u.x = h2u(__floats2half2_rn(a.x, a.y));
        u.y = h2u(__floats2half2_rn(a.z, a.w));
        u.z = h2u(__floats2half2_rn(b.x, b.y));
        u.w = h2u(__floats2half2_rn(b.z, b.w));
        *(uint4*)(xs + (size_t)t * XSTR + m * FIN) = u;
    }
    __syncthreads();

    const int t    = tid & (TB - 1);
    const int warp = tid >> 5;
    const __half* xrow = xs + (size_t)t * XSTR;
    const float2  z2   = make_float2(0.0f, 0.0f);

    // === Phase A: sparse aggregate + MLP, node pairs, g -> shared (fp32) ===
    #pragma unroll
    for (int p = 0; p < 2; p++) {
        const int na = warp * 4 + p * 2;   // pair (na, na+1)

        float2 accA[4], accB[4];
        #pragma unroll
        for (int q = 0; q < 4; q++) { accA[q] = z2; accB[q] = z2; }

        // sparse S1 for node na
        {
            const int dg = sdeg[na];
            const float* vr = svals + na * NP;
            const unsigned short* ir = sidx + na * NP;
            #pragma unroll 2
            for (int e = 0; e < dg; e++) {
                float a = vr[e];                       // warp broadcast
                int   m = ir[e];                       // warp broadcast
                float2 a2 = make_float2(a, a);
                uint4 xr = *(const uint4*)(xrow + m * FIN);
                accA[0] = ffma2(a2, __half22float2(*reinterpret_cast<const __half2*>(&xr.x)), accA[0]);
                accA[1] = ffma2(a2, __half22float2(*reinterpret_cast<const __half2*>(&xr.y)), accA[1]);
                accA[2] = ffma2(a2, __half22float2(*reinterpret_cast<const __half2*>(&xr.z)), accA[2]);
                accA[3] = ffma2(a2, __half22float2(*reinterpret_cast<const __half2*>(&xr.w)), accA[3]);
            }
        }
        // sparse S1 for node na+1
        {
            const int nb = na + 1;
            const int dg = sdeg[nb];
            const float* vr = svals + nb * NP;
            const unsigned short* ir = sidx + nb * NP;
            #pragma unroll 2
            for (int e = 0; e < dg; e++) {
                float a = vr[e];
                int   m = ir[e];
                float2 a2 = make_float2(a, a);
                uint4 xr = *(const uint4*)(xrow + m * FIN);
                accB[0] = ffma2(a2, __half22float2(*reinterpret_cast<const __half2*>(&xr.x)), accB[0]);
                accB[1] = ffma2(a2, __half22float2(*reinterpret_cast<const __half2*>(&xr.y)), accB[1]);
                accB[2] = ffma2(a2, __half22float2(*reinterpret_cast<const __half2*>(&xr.z)), accB[2]);
                accB[3] = ffma2(a2, __half22float2(*reinterpret_cast<const __half2*>(&xr.w)), accB[3]);
            }
        }

        // MLP for the pair: g = relu(acc @ W1) @ W2
        float2 gA[8], gB[8];
        #pragma unroll
        for (int q = 0; q < 8; q++) { gA[q] = z2; gB[q] = z2; }

        #pragma unroll 4
        for (int j = 0; j < H1C; j++) {
            const float4 w1a = *(const float4*)(W1t + j * FIN);
            const float4 w1b = *(const float4*)(W1t + j * FIN + 4);
            const float2 w0 = make_float2(w1a.x, w1a.y);
            const float2 w1v = make_float2(w1a.z, w1a.w);
            const float2 w2v = make_float2(w1b.x, w1b.y);
            const float2 w3 = make_float2(w1b.z, w1b.w);

            float2 hA2 = ffma2(accA[0], w0, z2);
            hA2 = ffma2(accA[1], w1v, hA2);
            hA2 = ffma2(accA[2], w2v, hA2);
            hA2 = ffma2(accA[3], w3, hA2);
            const float hA = fmaxf(hA2.x + hA2.y, 0.0f);
            const float2 hAp = make_float2(hA, hA);

            float2 hB2 = ffma2(accB[0], w0, z2);
            hB2 = ffma2(accB[1], w1v, hB2);
            hB2 = ffma2(accB[2], w2v, hB2);
            hB2 = ffma2(accB[3], w3, hB2);
            const float hB = fmaxf(hB2.x + hB2.y, 0.0f);
            const float2 hBp = make_float2(hB, hB);

            const float4* w2row = (const float4*)(W2s + j * H2C);
            #pragma unroll
            for (int q = 0; q < 4; q++) {
                float4 w = w2row[q];
                float2 wlo = make_float2(w.x, w.y);
                float2 whi = make_float2(w.z, w.w);
                gA[2*q]   = ffma2(hAp, wlo, gA[2*q]);
                gA[2*q+1] = ffma2(hAp, whi, gA[2*q+1]);
                gB[2*q]   = ffma2(hBp, wlo, gB[2*q]);
                gB[2*q+1] = ffma2(hBp, whi, gB[2*q+1]);
            }
        }

        // store g rows (fp32) to shared
        float* ga = gs + (size_t)t * GSTR + na * H2C;
        #pragma unroll
        for (int q = 0; q < 4; q++)
            *(float4*)(ga + q * 4) =
                make_float4(gA[2*q].x, gA[2*q].y, gA[2*q+1].x, gA[2*q+1].y);
        float* gb = ga + H2C;
        #pragma unroll
        for (int q = 0; q < 4; q++)
            *(float4*)(gb + q * 4) =
                make_float4(gB[2*q].x, gB[2*q].y, gB[2*q+1].x, gB[2*q+1].y);
    }
    __syncthreads();

    // === Phase B: sparse out = sigmoid(adj_n @ g) ===
    const float* gt = gs + (size_t)t * GSTR;
    #pragma unroll
    for (int i = 0; i < 4; i++) {
        const int n = warp * 4 + i;
        if (n >= NN) break;                 // padded nodes: no output
        const int dg = sdeg[n];
        const float* vr = svals + n * NP;
        const unsigned short* ir = sidx + n * NP;

        float2 o[8];
        #pragma unroll
        for (int q = 0; q < 8; q++) o[q] = z2;

        #pragma unroll 2
        for (int e = 0; e < dg; e++) {
            float a = vr[e];                // warp broadcast
            int   m = ir[e];                // warp broadcast
            float2 a2 = make_float2(a, a);
            const float4* gm = (const float4*)(gt + m * H2C);
            #pragma unroll
            for (int q = 0; q < 4; q++) {
                float4 g4 = gm[q];
                o[2*q]   = ffma2(a2, make_float2(g4.x, g4.y), o[2*q]);
                o[2*q+1] = ffma2(a2, make_float2(g4.z, g4.w), o[2*q+1]);
            }
        }

        float* op = out + ((size_t)(bt0 + t) * NN + n) * H2C;
        #pragma unroll
        for (int q = 0; q < 4; q++) {
            float4 r;
            r.x = __fdividef(1.0f, 1.0f + __expf(-o[2*q].x));
            r.y = __fdividef(1.0f, 1.0f + __expf(-o[2*q].y));
            r.z = __fdividef(1.0f, 1.0f + __expf(-o[2*q+1].x));
            r.w = __fdividef(1.0f, 1.0f + __expf(-o[2*q+1].y));
            *(float4*)(op + q * 4) = r;
        }
    }
}

// ---------------------------------------------------------------------------
extern "C" void kernel_launch(void* const* d_in, const int* in_sizes, int n_in,
                              void* d_out, int out_size) {
    const float* x   = (const float*)d_in[0];
    const float* adj = (const float*)d_in[1];
    const float* W1  = (const float*)d_in[2];
    const float* W2  = (const float*)d_in[3];
    float* out = (float*)d_out;

    const size_t smem =
        (size_t)(TB * GSTR + NP * NP + FIN * H1C + H1C * H2C) * sizeof(float) +
        (size_t)(TB * XSTR) * sizeof(__half) +
        (size_t)(NP * NP) * sizeof(unsigned short) +
        (size_t)NP * sizeof(int);          // 217760 B -> 1 block/SM
    cudaFuncSetAttribute(gcn_fused,
                         cudaFuncAttributeMaxDynamicSharedMemorySize,
                         (int)smem);

    prep_kernel<<<1, 128>>>(adj);
    gcn_fused<<<BT_TOTAL / TB, NTHREADS, smem>>>(x, W1, W2, out);
}